// round 14
// baseline (speedup 1.0000x reference)
#include <cuda_runtime.h>

// ---------------------------------------------------------------------------
// ResonantComplexProjection
//   theta[b,n,i] = x[b,i] / (1+|W[n,i]|) + B[n,i]
//   idx = floor(theta * 4096/2pi) mod 4096   (LUT sin/cos, 4096 entries)
//   cos_sum[b,n] = sum_i cos_lut[idx];  sin_sum likewise
//   real = cos_sum @ Wr^T ; imag = sin_sum @ Wi^T
// Shapes: batch=256, in_f=512, n_neur=1024, out_f=512
// ---------------------------------------------------------------------------

#define LUT_HALF 4608                  // table covers k in [-4608, 4608)
#define LUT_N    (2 * LUT_HALF)        // 9216 packed entries {cos16|sin16}
#define SMEM_MAIN (LUT_N * 4 + 2048)   // 36KB LUT + 2KB x tile = 38912 B
#define LUT_SCALE 16384.0f             // int16 quantization scale (2^14)

static __device__ unsigned g_lut32[LUT_N];     // {(s16)(cos*16384)<<16 | (u16)(s16)(sin*16384)}
static __device__ float4 g_rsbs[256 * 1024];   // [ipair][n] -> {rs0, rs1, bs0, bs1}
static __device__ int2   g_sums[4 * 262144];   // [iq][b][n] -> (sin_acc, cos_acc) int32
static __device__ float  g_A[2 * 262144];      // [p][b][k]: p0=cos, p1=sin
static __device__ float  g_part[8][262144];    // [ksplit][p*131072 + b*512 + o]

// ---------------------------------------------------------------------------
// Fused init: blocks [0,18) build the int16 LUT; blocks [18,1042) build rs/bs.
// ---------------------------------------------------------------------------

__global__ void k_init(const float* __restrict__ W, const float* __restrict__ B) {
    const int bid = blockIdx.x;
    const int tid = threadIdx.x;
    if (bid < 18) {
        int t = bid * 256 + tid;                   // < 4608
        const float step = (float)(6.283185307179586476925287 / 4096.0);
        int k0 = 2 * t - LUT_HALF;
        int j0 = k0 & 4095;                        // floor-mod 4096 (matches Python %)
        int j1 = (k0 + 1) & 4095;
        float a0 = (float)j0 * step;
        float a1 = (float)j1 * step;
        int s0 = __float2int_rn(sinf(a0) * LUT_SCALE);   // |v| <= 16384, fits s16
        int c0 = __float2int_rn(cosf(a0) * LUT_SCALE);
        int s1 = __float2int_rn(sinf(a1) * LUT_SCALE);
        int c1 = __float2int_rn(cosf(a1) * LUT_SCALE);
        unsigned w0 = ((unsigned)(unsigned short)(short)c0 << 16) | (unsigned short)(short)s0;
        unsigned w1 = ((unsigned)(unsigned short)(short)c1 << 16) | (unsigned short)(short)s1;
        ((uint2*)g_lut32)[t] = make_uint2(w0, w1);
    } else {
        int e = (bid - 18) * 256 + tid;            // < 262144
        int n  = e & 1023;
        int ip = e >> 10;
        const float S = (float)(4096.0 / 6.283185307179586476925287);
        float2 w = ((const float2*)(W + n * 512))[ip];
        float2 b = ((const float2*)(B + n * 512))[ip];
        float4 v;
        v.x = S / (1.0f + fabsf(w.x));
        v.y = S / (1.0f + fabsf(w.y));
        v.z = S * b.x - 0.5f;                      // fold floor(v)=round(v-0.5) shift
        v.w = S * b.y - 0.5f;
        g_rsbs[e] = v;                             // e = ip*1024 + n
    }
}

// ---------------------------------------------------------------------------
// Packed helpers
// ---------------------------------------------------------------------------

__device__ __forceinline__ unsigned long long fma2_(unsigned long long a,
                                                    unsigned long long b,
                                                    unsigned long long c) {
    unsigned long long d;
    asm("fma.rn.f32x2 %0, %1, %2, %3;" : "=l"(d) : "l"(a), "l"(b), "l"(c));
    return d;
}
__device__ __forceinline__ unsigned long long add2_(unsigned long long a,
                                                    unsigned long long b) {
    unsigned long long d;
    asm("add.rn.f32x2 %0, %1, %2;" : "=l"(d) : "l"(a), "l"(b));
    return d;
}
__device__ __forceinline__ unsigned lds32_(unsigned a) {
    unsigned v;
    asm("ld.shared.b32 %0, [%1];" : "=r"(v) : "r"(a));
    return v;
}
// dp2a.lo: d = a.h0*b.b0 + a.h1*b.b1 + c
__device__ __forceinline__ int dp2a_(unsigned a, unsigned b, int c) {
    int d;
    asm("dp2a.lo.s32.s32 %0, %1, %2, %3;" : "=r"(d) : "r"(a), "r"(b), "r"(c));
    return d;
}
// 4-byte async copy gmem -> smem (LDGSTS): no register round-trip.
__device__ __forceinline__ void cpa4_(unsigned saddr, const float* gptr) {
    asm volatile("cp.async.ca.shared.global [%0], [%1], 4;" :: "r"(saddr), "l"(gptr));
}

// ---------------------------------------------------------------------------
// k_main (UNCHANGED — proven R12): 296 blocks, strided 1024 fine tiles,
// thread = 1 neuron x 4 batches; two ip per step via one LDS.128 broadcast;
// int16 LUT via LDS.32; prmt+dp2a exact integer accumulation.
// ---------------------------------------------------------------------------

__global__ __launch_bounds__(256, 2) void k_main(const float* __restrict__ x) {
    extern __shared__ unsigned char smem[];
    uint4* lutv = (uint4*)smem;
    unsigned long long* xs2 = (unsigned long long*)(smem + LUT_N * 4);  // [4 b][64 ip]

    const int tid = threadIdx.x;

#pragma unroll
    for (int t = 0; t < (LUT_N / 4) / 256; t++)        // stage 36KB LUT (9 iters)
        lutv[tid + t * 256] = ((const uint4*)g_lut32)[tid + t * 256];

    const unsigned cbase =
        (unsigned)__cvta_generic_to_shared(smem) + (unsigned)(LUT_HALF * 4) - 0x2D000000u;
    const unsigned long long MAGIC2 = 0x4B4000004B400000ULL;
    const unsigned ONES = 0x0101u;        // dp2a: +1 weights for both halves

    const int lb  = tid >> 6;            // x-loader batch 0..3
    const int ipl = tid & 63;            // x-loader ipair 0..63

    for (int t = blockIdx.x; t < 1024; t += 296) {
        const int nt = t & 3;
        const int iq = (t >> 2) & 3;     // i-quarter (64 ipairs)
        const int bg = t >> 4;           // batch group of 4 (0..63)

        __syncthreads();                 // protect xs2 readers of previous tile
        xs2[tid] = ((const unsigned long long*)x)[((bg << 2) + lb) * 256 + (iq << 6) + ipl];
        __syncthreads();

        const int n = (nt << 8) + tid;
        const ulonglong2* rb =
            (const ulonglong2*)g_rsbs + (size_t)(iq << 6) * 1024 + n;

        int accS[4], accC[4];
#pragma unroll
        for (int b = 0; b < 4; b++) { accS[b] = 0; accC[b] = 0; }

#pragma unroll 2
        for (int ip = 0; ip < 64; ip += 2) {
            ulonglong2 rv0 = __ldg(rb + ip * 1024);        // {rs0,rs1},{bs0,bs1}
            ulonglong2 rv1 = __ldg(rb + (ip + 1) * 1024);
#pragma unroll
            for (int b = 0; b < 4; b++) {
                ulonglong2 xp2 = *(const ulonglong2*)&xs2[(b << 6) + ip];  // LDS.128 bcast

                unsigned long long w0 = add2_(fma2_(xp2.x, rv0.x, rv0.y), MAGIC2);
                unsigned q0l, q0h;
                asm("mov.b64 {%0, %1}, %2;" : "=r"(q0l), "=r"(q0h) : "l"(w0));
                unsigned e0 = lds32_(q0l * 4u + cbase);    // {cos16|sin16}
                unsigned e1 = lds32_(q0h * 4u + cbase);
                unsigned ss0, cc0;
                asm("prmt.b32 %0, %1, %2, 0x5410;" : "=r"(ss0) : "r"(e0), "r"(e1));
                asm("prmt.b32 %0, %1, %2, 0x7632;" : "=r"(cc0) : "r"(e0), "r"(e1));
                accS[b] = dp2a_(ss0, ONES, accS[b]);
                accC[b] = dp2a_(cc0, ONES, accC[b]);

                unsigned long long w1 = add2_(fma2_(xp2.y, rv1.x, rv1.y), MAGIC2);
                unsigned q1l, q1h;
                asm("mov.b64 {%0, %1}, %2;" : "=r"(q1l), "=r"(q1h) : "l"(w1));
                unsigned e2 = lds32_(q1l * 4u + cbase);
                unsigned e3 = lds32_(q1h * 4u + cbase);
                unsigned ss1, cc1;
                asm("prmt.b32 %0, %1, %2, 0x5410;" : "=r"(ss1) : "r"(e2), "r"(e3));
                asm("prmt.b32 %0, %1, %2, 0x7632;" : "=r"(cc1) : "r"(e2), "r"(e3));
                accS[b] = dp2a_(ss1, ONES, accS[b]);
                accC[b] = dp2a_(cc1, ONES, accC[b]);
            }
        }

        int2* sp = g_sums + (size_t)iq * 262144 + (size_t)(bg << 2) * 1024 + n;
#pragma unroll
        for (int b = 0; b < 4; b++) sp[(size_t)b * 1024] = make_int2(accS[b], accC[b]);
    }
}

// ---------------------------------------------------------------------------
// k_comb (UNCHANGED — proven): integer-sum 4 quarters exactly, scale once.
// ---------------------------------------------------------------------------

__global__ void k_comb() {
    int e = blockIdx.x * 256 + threadIdx.x;            // < 131072 int4s/quarter
    const int4* p0 = (const int4*)g_sums;              // {s0,c0,s1,c1}
    const int4* p1 = (const int4*)(g_sums + 262144);
    const int4* p2 = (const int4*)(g_sums + 2 * 262144);
    const int4* p3 = (const int4*)(g_sums + 3 * 262144);
    int4 a = p0[e], b = p1[e], c = p2[e], d = p3[e];
    int s0 = (a.x + b.x) + (c.x + d.x);
    int c0 = (a.y + b.y) + (c.y + d.y);
    int s1 = (a.z + b.z) + (c.z + d.z);
    int c1 = (a.w + b.w) + (c.w + d.w);
    const float SC = 1.0f / LUT_SCALE;
    ((float2*)g_A)[e]            = make_float2((float)c0 * SC, (float)c1 * SC); // cos
    ((float2*)(g_A + 262144))[e] = make_float2((float)s0 * SC, (float)s1 * SC); // sin
}

// ---------------------------------------------------------------------------
// k_gemm6: same 64x64 tile / 4x4 microtile / 8 K-splits / kk order as the
// proven gemm4 (bitwise-identical math), with the load path rebuilt:
//  (1) cp.async (LDGSTS) gmem->smem: no prefetch registers -> ~45 regs ->
//      __launch_bounds__(256,5): 5 blocks/SM, 40 warps (occ 39%->~62%),
//      512 blocks still a single wave (740 slots).
//  (2) BK 16->32: 4 chunks, 4 barriers (was 8); each async chunk flies under
//      a full 32-kk FMA block (~700 cyc >> L2 latency).
// Per chunk: wait_group 0 (only c(kc) pending) -> ONE __syncthreads (also
// closes compute of c(kc-1), making its buffer safe to refill) -> issue
// c(kc+1) -> compute c(kc).
// ---------------------------------------------------------------------------

#define BK2 32
#define LDP 68    // smem row stride in floats (float4-aligned)

__global__ __launch_bounds__(256, 5) void k_gemm6(const float* __restrict__ Wr,
                                                  const float* __restrict__ Wi) {
    __shared__ float As[2][BK2][LDP];
    __shared__ float Bs[2][BK2][LDP];

    const int tid = threadIdx.x;
    const int b0 = blockIdx.x << 6;
    const int o0 = blockIdx.y << 6;
    const int z  = blockIdx.z;
    const int pp = z >> 3;               // 0=real(cos), 1=imag(sin)
    const int s  = z & 7;                // K-split (128 each)

    const float* Ap = g_A + pp * 262144;
    const float* Wp = pp ? Wi : Wr;

    const int tx = tid & 15, ty = tid >> 4;
    const int lk  = tid & 31;            // k within chunk (coalesced gmem)
    const int lmb = tid >> 5;            // row group 0..7 (rows lmb+8t)
    const int kbase = s << 7;

    const unsigned as_base = (unsigned)__cvta_generic_to_shared(&As[0][0][0]);
    const unsigned bs_base = (unsigned)__cvta_generic_to_shared(&Bs[0][0][0]);
    const unsigned bufstride = (unsigned)(BK2 * LDP * 4);

    // issue all 16 cp.async for chunk kc into buffer buf
    auto issue = [&](int kc, int buf) {
        const int k0 = kbase + (kc << 5);
        const unsigned soff = (unsigned)buf * bufstride + (unsigned)(lk * LDP) * 4u;
#pragma unroll
        for (int t = 0; t < 8; t++) {
            const int row = lmb + (t << 3);
            cpa4_(as_base + soff + (unsigned)row * 4u,
                  Ap + (size_t)(b0 + row) * 1024 + k0 + lk);
            cpa4_(bs_base + soff + (unsigned)row * 4u,
                  Wp + (size_t)(o0 + row) * 1024 + k0 + lk);
        }
        asm volatile("cp.async.commit_group;" ::: "memory");
    };

    float acc[4][4] = {};

    issue(0, 0);                          // prologue

#pragma unroll 1
    for (int kc = 0; kc < 4; kc++) {
        const int cur = kc & 1;
        asm volatile("cp.async.wait_group 0;" ::: "memory");  // c(kc) arrived
        __syncthreads();                  // + all threads done with buffer cur^1
        if (kc < 3) issue(kc + 1, cur ^ 1);

#pragma unroll
        for (int kk = 0; kk < BK2; kk++) {
            float4 a4 = *(const float4*)&As[cur][kk][ty << 2];  // warp broadcast
            float4 b4 = *(const float4*)&Bs[cur][kk][tx << 2];
            float av[4] = {a4.x, a4.y, a4.z, a4.w};
            float bv[4] = {b4.x, b4.y, b4.z, b4.w};
#pragma unroll
            for (int i = 0; i < 4; i++)
#pragma unroll
                for (int j = 0; j < 4; j++)
                    acc[i][j] = fmaf(av[i], bv[j], acc[i][j]);
        }
    }

    float* dst = &g_part[s][pp * 131072 + (size_t)(b0 + (ty << 2)) * 512 + o0 + (tx << 2)];
#pragma unroll
    for (int i = 0; i < 4; i++)
        *(float4*)(dst + (size_t)i * 512) =
            make_float4(acc[i][0], acc[i][1], acc[i][2], acc[i][3]);
}

// ---------------------------------------------------------------------------
// k_reduce (UNCHANGED — proven): 8-way, float4-vectorized, fixed order.
// ---------------------------------------------------------------------------

__global__ void k_reduce(float* __restrict__ out) {
    int e = blockIdx.x * 256 + threadIdx.x;     // < 65536 float4s
    float4 p0 = ((const float4*)g_part[0])[e];
    float4 p1 = ((const float4*)g_part[1])[e];
    float4 p2 = ((const float4*)g_part[2])[e];
    float4 p3 = ((const float4*)g_part[3])[e];
    float4 p4 = ((const float4*)g_part[4])[e];
    float4 p5 = ((const float4*)g_part[5])[e];
    float4 p6 = ((const float4*)g_part[6])[e];
    float4 p7 = ((const float4*)g_part[7])[e];
    float4 r;
    r.x = ((p0.x + p1.x) + (p2.x + p3.x)) + ((p4.x + p5.x) + (p6.x + p7.x));
    r.y = ((p0.y + p1.y) + (p2.y + p3.y)) + ((p4.y + p5.y) + (p6.y + p7.y));
    r.z = ((p0.z + p1.z) + (p2.z + p3.z)) + ((p4.z + p5.z) + (p6.z + p7.z));
    r.w = ((p0.w + p1.w) + (p2.w + p3.w)) + ((p4.w + p5.w) + (p6.w + p7.w));
    ((float4*)out)[e] = r;
}

// ---------------------------------------------------------------------------

extern "C" void kernel_launch(void* const* d_in, const int* in_sizes, int n_in,
                              void* d_out, int out_size) {
    const float* x  = (const float*)d_in[0];
    const float* W  = (const float*)d_in[1];
    const float* B  = (const float*)d_in[2];
    const float* Wr = (const float*)d_in[3];
    const float* Wi = (const float*)d_in[4];
    float* out = (float*)d_out;

    cudaFuncSetAttribute(k_main, cudaFuncAttributeMaxDynamicSharedMemorySize, SMEM_MAIN);

    k_init<<<18 + 1024, 256>>>(W, B);
    k_main<<<296, 256, SMEM_MAIN>>>(x);
    k_comb<<<512, 256>>>();
    k_gemm6<<<dim3(4, 8, 16), 256>>>(Wr, Wi);
    k_reduce<<<256, 256>>>(out);
}

// round 16
// speedup vs baseline: 1.0343x; 1.0343x over previous
#include <cuda_runtime.h>

// ---------------------------------------------------------------------------
// ResonantComplexProjection
//   theta[b,n,i] = x[b,i] / (1+|W[n,i]|) + B[n,i]
//   idx = floor(theta * 4096/2pi) mod 4096   (LUT sin/cos, 4096 entries)
//   cos_sum[b,n] = sum_i cos_lut[idx];  sin_sum likewise
//   real = cos_sum @ Wr^T ; imag = sin_sum @ Wi^T
// Shapes: batch=256, in_f=512, n_neur=1024, out_f=512
// ---------------------------------------------------------------------------

#define LUT_HALF 4608                  // table covers k in [-4608, 4608)
#define LUT_N    (2 * LUT_HALF)        // 9216 packed entries {cos16|sin16}
#define SMEM_MAIN (LUT_N * 4 + 2048)   // 36KB LUT + 2KB x tile = 38912 B
#define LUT_SCALE 16384.0f             // int16 quantization scale (2^14)

static __device__ unsigned g_lut32[LUT_N];     // {(s16)(cos*16384)<<16 | (u16)(s16)(sin*16384)}
static __device__ float4 g_rsbs[256 * 1024];   // [ipair][n] -> {rs0, rs1, bs0, bs1}
static __device__ int    g_sumS[262144];       // [b][n] sin integer sum (atomic, exact)
static __device__ int    g_sumC[262144];       // [b][n] cos integer sum (atomic, exact)
static __device__ float  g_part[8][262144];    // [ksplit][p*131072 + b*512 + o]

// ---------------------------------------------------------------------------
// Fused init: blocks [0,18) build the int16 LUT; [18,1042) build rs/bs;
// [1042,1298) zero the atomic sum planes.
// R15 FIX: each plane is 262144 ints = 65536 int4s -> need 256 zeroing
// blocks (256*256 threads, 1 int4 per plane per thread). R14 had 128,
// leaving half of each plane stale -> sums accumulated across graph
// replays (post-timing divergence). Zeroing runs every replay, ordered
// before k_main by stream order.
// ---------------------------------------------------------------------------

__global__ void k_init(const float* __restrict__ W, const float* __restrict__ B) {
    const int bid = blockIdx.x;
    const int tid = threadIdx.x;
    if (bid < 18) {
        int t = bid * 256 + tid;                   // < 4608
        const float step = (float)(6.283185307179586476925287 / 4096.0);
        int k0 = 2 * t - LUT_HALF;
        int j0 = k0 & 4095;                        // floor-mod 4096 (matches Python %)
        int j1 = (k0 + 1) & 4095;
        float a0 = (float)j0 * step;
        float a1 = (float)j1 * step;
        int s0 = __float2int_rn(sinf(a0) * LUT_SCALE);   // |v| <= 16384, fits s16
        int c0 = __float2int_rn(cosf(a0) * LUT_SCALE);
        int s1 = __float2int_rn(sinf(a1) * LUT_SCALE);
        int c1 = __float2int_rn(cosf(a1) * LUT_SCALE);
        unsigned w0 = ((unsigned)(unsigned short)(short)c0 << 16) | (unsigned short)(short)s0;
        unsigned w1 = ((unsigned)(unsigned short)(short)c1 << 16) | (unsigned short)(short)s1;
        ((uint2*)g_lut32)[t] = make_uint2(w0, w1);
    } else if (bid < 18 + 1024) {
        int e = (bid - 18) * 256 + tid;            // < 262144
        int n  = e & 1023;
        int ip = e >> 10;
        const float S = (float)(4096.0 / 6.283185307179586476925287);
        float2 w = ((const float2*)(W + n * 512))[ip];
        float2 b = ((const float2*)(B + n * 512))[ip];
        float4 v;
        v.x = S / (1.0f + fabsf(w.x));
        v.y = S / (1.0f + fabsf(w.y));
        v.z = S * b.x - 0.5f;                      // fold floor(v)=round(v-0.5) shift
        v.w = S * b.y - 0.5f;
        g_rsbs[e] = v;                             // e = ip*1024 + n
    } else {
        int e = (bid - 1042) * 256 + tid;          // < 65536 int4s = FULL plane
        ((int4*)g_sumS)[e] = make_int4(0, 0, 0, 0);
        ((int4*)g_sumC)[e] = make_int4(0, 0, 0, 0);
    }
}

// ---------------------------------------------------------------------------
// Packed helpers
// ---------------------------------------------------------------------------

__device__ __forceinline__ unsigned long long fma2_(unsigned long long a,
                                                    unsigned long long b,
                                                    unsigned long long c) {
    unsigned long long d;
    asm("fma.rn.f32x2 %0, %1, %2, %3;" : "=l"(d) : "l"(a), "l"(b), "l"(c));
    return d;
}
__device__ __forceinline__ unsigned long long add2_(unsigned long long a,
                                                    unsigned long long b) {
    unsigned long long d;
    asm("add.rn.f32x2 %0, %1, %2;" : "=l"(d) : "l"(a), "l"(b));
    return d;
}
__device__ __forceinline__ unsigned lds32_(unsigned a) {
    unsigned v;
    asm("ld.shared.b32 %0, [%1];" : "=r"(v) : "r"(a));
    return v;
}
// dp2a.lo: d = a.h0*b.b0 + a.h1*b.b1 + c
__device__ __forceinline__ int dp2a_(unsigned a, unsigned b, int c) {
    int d;
    asm("dp2a.lo.s32.s32 %0, %1, %2, %3;" : "=r"(d) : "r"(a), "r"(b), "r"(c));
    return d;
}

// ---------------------------------------------------------------------------
// k_main v7 (unchanged from R14): math and schedule identical to proven R12
// (296 blocks, strided 1024 fine tiles, thread = 1 neuron x 4 batches,
// LDS.128 paired broadcast, int16 LUT via LDS.32, prmt+dp2a exact
// accumulation). Quarter partials land via integer atomicAdd (REDG, no
// return) into g_sumS/g_sumC — integer addition is order-independent and
// exact, so results are bit-identical and deterministic; k_comb is gone.
// ---------------------------------------------------------------------------

__global__ __launch_bounds__(256, 2) void k_main(const float* __restrict__ x) {
    extern __shared__ unsigned char smem[];
    uint4* lutv = (uint4*)smem;
    unsigned long long* xs2 = (unsigned long long*)(smem + LUT_N * 4);  // [4 b][64 ip]

    const int tid = threadIdx.x;

#pragma unroll
    for (int t = 0; t < (LUT_N / 4) / 256; t++)        // stage 36KB LUT (9 iters)
        lutv[tid + t * 256] = ((const uint4*)g_lut32)[tid + t * 256];

    const unsigned cbase =
        (unsigned)__cvta_generic_to_shared(smem) + (unsigned)(LUT_HALF * 4) - 0x2D000000u;
    const unsigned long long MAGIC2 = 0x4B4000004B400000ULL;
    const unsigned ONES = 0x0101u;        // dp2a: +1 weights for both halves

    const int lb  = tid >> 6;            // x-loader batch 0..3
    const int ipl = tid & 63;            // x-loader ipair 0..63

    for (int t = blockIdx.x; t < 1024; t += 296) {
        const int nt = t & 3;
        const int iq = (t >> 2) & 3;     // i-quarter (64 ipairs)
        const int bg = t >> 4;           // batch group of 4 (0..63)

        __syncthreads();                 // protect xs2 readers of previous tile
        xs2[tid] = ((const unsigned long long*)x)[((bg << 2) + lb) * 256 + (iq << 6) + ipl];
        __syncthreads();

        const int n = (nt << 8) + tid;
        const ulonglong2* rb =
            (const ulonglong2*)g_rsbs + (size_t)(iq << 6) * 1024 + n;

        int accS[4], accC[4];
#pragma unroll
        for (int b = 0; b < 4; b++) { accS[b] = 0; accC[b] = 0; }

#pragma unroll 2
        for (int ip = 0; ip < 64; ip += 2) {
            ulonglong2 rv0 = __ldg(rb + ip * 1024);        // {rs0,rs1},{bs0,bs1}
            ulonglong2 rv1 = __ldg(rb + (ip + 1) * 1024);
#pragma unroll
            for (int b = 0; b < 4; b++) {
                ulonglong2 xp2 = *(const ulonglong2*)&xs2[(b << 6) + ip];  // LDS.128 bcast

                unsigned long long w0 = add2_(fma2_(xp2.x, rv0.x, rv0.y), MAGIC2);
                unsigned q0l, q0h;
                asm("mov.b64 {%0, %1}, %2;" : "=r"(q0l), "=r"(q0h) : "l"(w0));
                unsigned e0 = lds32_(q0l * 4u + cbase);    // {cos16|sin16}
                unsigned e1 = lds32_(q0h * 4u + cbase);
                unsigned ss0, cc0;
                asm("prmt.b32 %0, %1, %2, 0x5410;" : "=r"(ss0) : "r"(e0), "r"(e1));
                asm("prmt.b32 %0, %1, %2, 0x7632;" : "=r"(cc0) : "r"(e0), "r"(e1));
                accS[b] = dp2a_(ss0, ONES, accS[b]);
                accC[b] = dp2a_(cc0, ONES, accC[b]);

                unsigned long long w1 = add2_(fma2_(xp2.y, rv1.x, rv1.y), MAGIC2);
                unsigned q1l, q1h;
                asm("mov.b64 {%0, %1}, %2;" : "=r"(q1l), "=r"(q1h) : "l"(w1));
                unsigned e2 = lds32_(q1l * 4u + cbase);
                unsigned e3 = lds32_(q1h * 4u + cbase);
                unsigned ss1, cc1;
                asm("prmt.b32 %0, %1, %2, 0x5410;" : "=r"(ss1) : "r"(e2), "r"(e3));
                asm("prmt.b32 %0, %1, %2, 0x7632;" : "=r"(cc1) : "r"(e2), "r"(e3));
                accS[b] = dp2a_(ss1, ONES, accS[b]);
                accC[b] = dp2a_(cc1, ONES, accC[b]);
            }
        }

        const int base = (bg << 2) * 1024 + n;
#pragma unroll
        for (int b = 0; b < 4; b++) {
            atomicAdd(&g_sumS[base + b * 1024], accS[b]);   // REDG.ADD, exact
            atomicAdd(&g_sumC[base + b * 1024], accC[b]);
        }
    }
}

// ---------------------------------------------------------------------------
// k_gemm4 v3 (unchanged from R14): proven register-prefetch gemm4
// (double-buffered, one sync per chunk, outer `#pragma unroll 1`,
// 8 K-splits, (256,4)); A operand read from integer sum planes with the
// conversion ((float)i * 1/16384) fused into the prefetch path — value
// identical to the old k_comb output, so gemm math is bit-identical.
// ---------------------------------------------------------------------------

#define BK 16
#define LDP 68    // smem row stride in floats (float4-aligned)

__global__ __launch_bounds__(256, 4) void k_gemm4(const float* __restrict__ Wr,
                                                  const float* __restrict__ Wi) {
    __shared__ float As[2][BK][LDP];
    __shared__ float Bs[2][BK][LDP];

    const int tid = threadIdx.x;
    const int b0 = blockIdx.x << 6;
    const int o0 = blockIdx.y << 6;
    const int z  = blockIdx.z;
    const int pp = z >> 3;               // 0=real(cos), 1=imag(sin)
    const int s  = z & 7;                // K-split (128 each)

    const int* Aip = pp ? g_sumS : g_sumC;
    const float* Wp = pp ? Wi : Wr;
    const float SC = 1.0f / LUT_SCALE;

    const int tx = tid & 15, ty = tid >> 4;
    const int lk = tid & 15;             // k within chunk
    const int lm = tid >> 4;             // base row 0..15 (4 strided rows)
    const int kbase = s << 7;

    float ar[4], br[4];
#pragma unroll
    for (int t = 0; t < 4; t++) {
        ar[t] = (float)__ldg(Aip + (size_t)(b0 + lm + t * 16) * 1024 + kbase + lk) * SC;
        br[t] = Wp[(size_t)(o0 + lm + t * 16) * 1024 + kbase + lk];
    }
#pragma unroll
    for (int t = 0; t < 4; t++) {
        As[0][lk][lm + t * 16] = ar[t];
        Bs[0][lk][lm + t * 16] = br[t];
    }
    __syncthreads();

    float acc[4][4] = {};

#pragma unroll 1
    for (int kc = 0; kc < 8; kc++) {
        const int cur = kc & 1;
        if (kc < 7) {                     // prefetch next chunk into registers
            const int k0 = kbase + ((kc + 1) << 4);
#pragma unroll
            for (int t = 0; t < 4; t++) {
                ar[t] = (float)__ldg(Aip + (size_t)(b0 + lm + t * 16) * 1024 + k0 + lk) * SC;
                br[t] = Wp[(size_t)(o0 + lm + t * 16) * 1024 + k0 + lk];
            }
        }
#pragma unroll
        for (int kk = 0; kk < BK; kk++) {
            float4 a4 = *(const float4*)&As[cur][kk][ty << 2];  // warp broadcast
            float4 b4 = *(const float4*)&Bs[cur][kk][tx << 2];
            float av[4] = {a4.x, a4.y, a4.z, a4.w};
            float bv[4] = {b4.x, b4.y, b4.z, b4.w};
#pragma unroll
            for (int i = 0; i < 4; i++)
#pragma unroll
                for (int j = 0; j < 4; j++)
                    acc[i][j] = fmaf(av[i], bv[j], acc[i][j]);
        }
        if (kc < 7) {
            const int nxt = cur ^ 1;
#pragma unroll
            for (int t = 0; t < 4; t++) {
                As[nxt][lk][lm + t * 16] = ar[t];
                Bs[nxt][lk][lm + t * 16] = br[t];
            }
            __syncthreads();              // one barrier per chunk
        }
    }

    float* dst = &g_part[s][pp * 131072 + (size_t)(b0 + (ty << 2)) * 512 + o0 + (tx << 2)];
#pragma unroll
    for (int i = 0; i < 4; i++)
        *(float4*)(dst + (size_t)i * 512) =
            make_float4(acc[i][0], acc[i][1], acc[i][2], acc[i][3]);
}

// ---------------------------------------------------------------------------
// k_reduce (UNCHANGED — proven): 8-way, float4-vectorized, fixed order.
// ---------------------------------------------------------------------------

__global__ void k_reduce(float* __restrict__ out) {
    int e = blockIdx.x * 256 + threadIdx.x;     // < 65536 float4s
    float4 p0 = ((const float4*)g_part[0])[e];
    float4 p1 = ((const float4*)g_part[1])[e];
    float4 p2 = ((const float4*)g_part[2])[e];
    float4 p3 = ((const float4*)g_part[3])[e];
    float4 p4 = ((const float4*)g_part[4])[e];
    float4 p5 = ((const float4*)g_part[5])[e];
    float4 p6 = ((const float4*)g_part[6])[e];
    float4 p7 = ((const float4*)g_part[7])[e];
    float4 r;
    r.x = ((p0.x + p1.x) + (p2.x + p3.x)) + ((p4.x + p5.x) + (p6.x + p7.x));
    r.y = ((p0.y + p1.y) + (p2.y + p3.y)) + ((p4.y + p5.y) + (p6.y + p7.y));
    r.z = ((p0.z + p1.z) + (p2.z + p3.z)) + ((p4.z + p5.z) + (p6.z + p7.z));
    r.w = ((p0.w + p1.w) + (p2.w + p3.w)) + ((p4.w + p5.w) + (p6.w + p7.w));
    ((float4*)out)[e] = r;
}

// ---------------------------------------------------------------------------

extern "C" void kernel_launch(void* const* d_in, const int* in_sizes, int n_in,
                              void* d_out, int out_size) {
    const float* x  = (const float*)d_in[0];
    const float* W  = (const float*)d_in[1];
    const float* B  = (const float*)d_in[2];
    const float* Wr = (const float*)d_in[3];
    const float* Wi = (const float*)d_in[4];
    float* out = (float*)d_out;

    cudaFuncSetAttribute(k_main, cudaFuncAttributeMaxDynamicSharedMemorySize, SMEM_MAIN);

    k_init<<<18 + 1024 + 256, 256>>>(W, B);
    k_main<<<296, 256, SMEM_MAIN>>>(x);
    k_gemm4<<<dim3(4, 8, 16), 256>>>(Wr, Wi);
    k_reduce<<<256, 256>>>(out);
}

// round 17
// speedup vs baseline: 1.0363x; 1.0019x over previous
#include <cuda_runtime.h>

// ---------------------------------------------------------------------------
// ResonantComplexProjection
//   theta[b,n,i] = x[b,i] / (1+|W[n,i]|) + B[n,i]
//   idx = floor(theta * 4096/2pi) mod 4096   (LUT sin/cos, 4096 entries)
//   cos_sum[b,n] = sum_i cos_lut[idx];  sin_sum likewise
//   real = cos_sum @ Wr^T ; imag = sin_sum @ Wi^T
// Shapes: batch=256, in_f=512, n_neur=1024, out_f=512
// ---------------------------------------------------------------------------

#define LUT_HALF 4608                  // table covers k in [-4608, 4608)
#define LUT_N    (2 * LUT_HALF)        // 9216 packed entries {cos16|sin16}
#define SMEM_MAIN (LUT_N * 4 + 2048)   // 36KB LUT + 2KB x tile = 38912 B
#define LUT_SCALE 16384.0f             // int16 quantization scale (2^14)

static __device__ unsigned g_lut32[LUT_N];     // {(s16)(cos*16384)<<16 | (u16)(s16)(sin*16384)}
static __device__ float4 g_rsbs[256 * 1024];   // [ipair][n] -> {rs0, rs1, bs0, bs1}
static __device__ int    g_sumS[262144];       // [b][n] sin integer sum (atomic, exact)
static __device__ int    g_sumC[262144];       // [b][n] cos integer sum (atomic, exact)
static __device__ float  g_part[8][262144];    // [ksplit][p*131072 + b*512 + o]

// ---------------------------------------------------------------------------
// Fused init (UNCHANGED — proven R15): [0,18) int16 LUT; [18,1042) rs/bs;
// [1042,1298) zero the FULL atomic sum planes (65536 int4s per plane),
// every graph replay, ordered before k_main by stream order.
// ---------------------------------------------------------------------------

__global__ void k_init(const float* __restrict__ W, const float* __restrict__ B) {
    const int bid = blockIdx.x;
    const int tid = threadIdx.x;
    if (bid < 18) {
        int t = bid * 256 + tid;                   // < 4608
        const float step = (float)(6.283185307179586476925287 / 4096.0);
        int k0 = 2 * t - LUT_HALF;
        int j0 = k0 & 4095;                        // floor-mod 4096 (matches Python %)
        int j1 = (k0 + 1) & 4095;
        float a0 = (float)j0 * step;
        float a1 = (float)j1 * step;
        int s0 = __float2int_rn(sinf(a0) * LUT_SCALE);   // |v| <= 16384, fits s16
        int c0 = __float2int_rn(cosf(a0) * LUT_SCALE);
        int s1 = __float2int_rn(sinf(a1) * LUT_SCALE);
        int c1 = __float2int_rn(cosf(a1) * LUT_SCALE);
        unsigned w0 = ((unsigned)(unsigned short)(short)c0 << 16) | (unsigned short)(short)s0;
        unsigned w1 = ((unsigned)(unsigned short)(short)c1 << 16) | (unsigned short)(short)s1;
        ((uint2*)g_lut32)[t] = make_uint2(w0, w1);
    } else if (bid < 18 + 1024) {
        int e = (bid - 18) * 256 + tid;            // < 262144
        int n  = e & 1023;
        int ip = e >> 10;
        const float S = (float)(4096.0 / 6.283185307179586476925287);
        float2 w = ((const float2*)(W + n * 512))[ip];
        float2 b = ((const float2*)(B + n * 512))[ip];
        float4 v;
        v.x = S / (1.0f + fabsf(w.x));
        v.y = S / (1.0f + fabsf(w.y));
        v.z = S * b.x - 0.5f;                      // fold floor(v)=round(v-0.5) shift
        v.w = S * b.y - 0.5f;
        g_rsbs[e] = v;                             // e = ip*1024 + n
    } else {
        int e = (bid - 1042) * 256 + tid;          // < 65536 int4s = FULL plane
        ((int4*)g_sumS)[e] = make_int4(0, 0, 0, 0);
        ((int4*)g_sumC)[e] = make_int4(0, 0, 0, 0);
    }
}

// ---------------------------------------------------------------------------
// Packed helpers
// ---------------------------------------------------------------------------

__device__ __forceinline__ unsigned long long fma2_(unsigned long long a,
                                                    unsigned long long b,
                                                    unsigned long long c) {
    unsigned long long d;
    asm("fma.rn.f32x2 %0, %1, %2, %3;" : "=l"(d) : "l"(a), "l"(b), "l"(c));
    return d;
}
__device__ __forceinline__ unsigned long long add2_(unsigned long long a,
                                                    unsigned long long b) {
    unsigned long long d;
    asm("add.rn.f32x2 %0, %1, %2;" : "=l"(d) : "l"(a), "l"(b));
    return d;
}
__device__ __forceinline__ unsigned lds32_(unsigned a) {
    unsigned v;
    asm("ld.shared.b32 %0, [%1];" : "=r"(v) : "r"(a));
    return v;
}
// dp2a.lo: d = a.h0*b.b0 + a.h1*b.b1 + c
__device__ __forceinline__ int dp2a_(unsigned a, unsigned b, int c) {
    int d;
    asm("dp2a.lo.s32.s32 %0, %1, %2, %3;" : "=r"(d) : "r"(a), "r"(b), "r"(c));
    return d;
}

// ---------------------------------------------------------------------------
// k_main v7 (UNCHANGED — proven R15): 296 blocks, strided 1024 fine tiles,
// thread = 1 neuron x 4 batches, LDS.128 paired broadcast, int16 LUT via
// LDS.32, prmt+dp2a exact accumulation; partials via integer atomicAdd
// (REDG, exact, order-independent -> deterministic).
// ---------------------------------------------------------------------------

__global__ __launch_bounds__(256, 2) void k_main(const float* __restrict__ x) {
    extern __shared__ unsigned char smem[];
    uint4* lutv = (uint4*)smem;
    unsigned long long* xs2 = (unsigned long long*)(smem + LUT_N * 4);  // [4 b][64 ip]

    const int tid = threadIdx.x;

#pragma unroll
    for (int t = 0; t < (LUT_N / 4) / 256; t++)        // stage 36KB LUT (9 iters)
        lutv[tid + t * 256] = ((const uint4*)g_lut32)[tid + t * 256];

    const unsigned cbase =
        (unsigned)__cvta_generic_to_shared(smem) + (unsigned)(LUT_HALF * 4) - 0x2D000000u;
    const unsigned long long MAGIC2 = 0x4B4000004B400000ULL;
    const unsigned ONES = 0x0101u;        // dp2a: +1 weights for both halves

    const int lb  = tid >> 6;            // x-loader batch 0..3
    const int ipl = tid & 63;            // x-loader ipair 0..63

    for (int t = blockIdx.x; t < 1024; t += 296) {
        const int nt = t & 3;
        const int iq = (t >> 2) & 3;     // i-quarter (64 ipairs)
        const int bg = t >> 4;           // batch group of 4 (0..63)

        __syncthreads();                 // protect xs2 readers of previous tile
        xs2[tid] = ((const unsigned long long*)x)[((bg << 2) + lb) * 256 + (iq << 6) + ipl];
        __syncthreads();

        const int n = (nt << 8) + tid;
        const ulonglong2* rb =
            (const ulonglong2*)g_rsbs + (size_t)(iq << 6) * 1024 + n;

        int accS[4], accC[4];
#pragma unroll
        for (int b = 0; b < 4; b++) { accS[b] = 0; accC[b] = 0; }

#pragma unroll 2
        for (int ip = 0; ip < 64; ip += 2) {
            ulonglong2 rv0 = __ldg(rb + ip * 1024);        // {rs0,rs1},{bs0,bs1}
            ulonglong2 rv1 = __ldg(rb + (ip + 1) * 1024);
#pragma unroll
            for (int b = 0; b < 4; b++) {
                ulonglong2 xp2 = *(const ulonglong2*)&xs2[(b << 6) + ip];  // LDS.128 bcast

                unsigned long long w0 = add2_(fma2_(xp2.x, rv0.x, rv0.y), MAGIC2);
                unsigned q0l, q0h;
                asm("mov.b64 {%0, %1}, %2;" : "=r"(q0l), "=r"(q0h) : "l"(w0));
                unsigned e0 = lds32_(q0l * 4u + cbase);    // {cos16|sin16}
                unsigned e1 = lds32_(q0h * 4u + cbase);
                unsigned ss0, cc0;
                asm("prmt.b32 %0, %1, %2, 0x5410;" : "=r"(ss0) : "r"(e0), "r"(e1));
                asm("prmt.b32 %0, %1, %2, 0x7632;" : "=r"(cc0) : "r"(e0), "r"(e1));
                accS[b] = dp2a_(ss0, ONES, accS[b]);
                accC[b] = dp2a_(cc0, ONES, accC[b]);

                unsigned long long w1 = add2_(fma2_(xp2.y, rv1.x, rv1.y), MAGIC2);
                unsigned q1l, q1h;
                asm("mov.b64 {%0, %1}, %2;" : "=r"(q1l), "=r"(q1h) : "l"(w1));
                unsigned e2 = lds32_(q1l * 4u + cbase);
                unsigned e3 = lds32_(q1h * 4u + cbase);
                unsigned ss1, cc1;
                asm("prmt.b32 %0, %1, %2, 0x5410;" : "=r"(ss1) : "r"(e2), "r"(e3));
                asm("prmt.b32 %0, %1, %2, 0x7632;" : "=r"(cc1) : "r"(e2), "r"(e3));
                accS[b] = dp2a_(ss1, ONES, accS[b]);
                accC[b] = dp2a_(cc1, ONES, accC[b]);
            }
        }

        const int base = (bg << 2) * 1024 + n;
#pragma unroll
        for (int b = 0; b < 4; b++) {
            atomicAdd(&g_sumS[base + b * 1024], accS[b]);   // REDG.ADD, exact
            atomicAdd(&g_sumC[base + b * 1024], accC[b]);
        }
    }
}

// ---------------------------------------------------------------------------
// k_gemm4 v3 (UNCHANGED — proven R15): register-prefetch double-buffered
// GEMM, one sync per chunk, outer `#pragma unroll 1`, 8 K-splits, (256,4);
// A operand converted from integer sums in the prefetch path.
// ---------------------------------------------------------------------------

#define BK 16
#define LDP 68    // smem row stride in floats (float4-aligned)

__global__ __launch_bounds__(256, 4) void k_gemm4(const float* __restrict__ Wr,
                                                  const float* __restrict__ Wi) {
    __shared__ float As[2][BK][LDP];
    __shared__ float Bs[2][BK][LDP];

    const int tid = threadIdx.x;
    const int b0 = blockIdx.x << 6;
    const int o0 = blockIdx.y << 6;
    const int z  = blockIdx.z;
    const int pp = z >> 3;               // 0=real(cos), 1=imag(sin)
    const int s  = z & 7;                // K-split (128 each)

    const int* Aip = pp ? g_sumS : g_sumC;
    const float* Wp = pp ? Wi : Wr;
    const float SC = 1.0f / LUT_SCALE;

    const int tx = tid & 15, ty = tid >> 4;
    const int lk = tid & 15;             // k within chunk
    const int lm = tid >> 4;             // base row 0..15 (4 strided rows)
    const int kbase = s << 7;

    float ar[4], br[4];
#pragma unroll
    for (int t = 0; t < 4; t++) {
        ar[t] = (float)__ldg(Aip + (size_t)(b0 + lm + t * 16) * 1024 + kbase + lk) * SC;
        br[t] = Wp[(size_t)(o0 + lm + t * 16) * 1024 + kbase + lk];
    }
#pragma unroll
    for (int t = 0; t < 4; t++) {
        As[0][lk][lm + t * 16] = ar[t];
        Bs[0][lk][lm + t * 16] = br[t];
    }
    __syncthreads();

    float acc[4][4] = {};

#pragma unroll 1
    for (int kc = 0; kc < 8; kc++) {
        const int cur = kc & 1;
        if (kc < 7) {                     // prefetch next chunk into registers
            const int k0 = kbase + ((kc + 1) << 4);
#pragma unroll
            for (int t = 0; t < 4; t++) {
                ar[t] = (float)__ldg(Aip + (size_t)(b0 + lm + t * 16) * 1024 + k0 + lk) * SC;
                br[t] = Wp[(size_t)(o0 + lm + t * 16) * 1024 + k0 + lk];
            }
        }
#pragma unroll
        for (int kk = 0; kk < BK; kk++) {
            float4 a4 = *(const float4*)&As[cur][kk][ty << 2];  // warp broadcast
            float4 b4 = *(const float4*)&Bs[cur][kk][tx << 2];
            float av[4] = {a4.x, a4.y, a4.z, a4.w};
            float bv[4] = {b4.x, b4.y, b4.z, b4.w};
#pragma unroll
            for (int i = 0; i < 4; i++)
#pragma unroll
                for (int j = 0; j < 4; j++)
                    acc[i][j] = fmaf(av[i], bv[j], acc[i][j]);
        }
        if (kc < 7) {
            const int nxt = cur ^ 1;
#pragma unroll
            for (int t = 0; t < 4; t++) {
                As[nxt][lk][lm + t * 16] = ar[t];
                Bs[nxt][lk][lm + t * 16] = br[t];
            }
            __syncthreads();              // one barrier per chunk
        }
    }

    float* dst = &g_part[s][pp * 131072 + (size_t)(b0 + (ty << 2)) * 512 + o0 + (tx << 2)];
#pragma unroll
    for (int i = 0; i < 4; i++)
        *(float4*)(dst + (size_t)i * 512) =
            make_float4(acc[i][0], acc[i][1], acc[i][2], acc[i][3]);
}

// ---------------------------------------------------------------------------
// k_reduce v4: same fixed pairwise order (bit-identical output), but float2
// granularity -> 131072 threads (512 blocks) instead of 65536: twice the
// warps and outstanding loads against L2 latency. Same bytes moved.
// ---------------------------------------------------------------------------

__global__ void k_reduce(float* __restrict__ out) {
    int e = blockIdx.x * 256 + threadIdx.x;     // < 131072 float2s
    float2 p0 = __ldg((const float2*)g_part[0] + e);
    float2 p1 = __ldg((const float2*)g_part[1] + e);
    float2 p2 = __ldg((const float2*)g_part[2] + e);
    float2 p3 = __ldg((const float2*)g_part[3] + e);
    float2 p4 = __ldg((const float2*)g_part[4] + e);
    float2 p5 = __ldg((const float2*)g_part[5] + e);
    float2 p6 = __ldg((const float2*)g_part[6] + e);
    float2 p7 = __ldg((const float2*)g_part[7] + e);
    float2 r;
    r.x = ((p0.x + p1.x) + (p2.x + p3.x)) + ((p4.x + p5.x) + (p6.x + p7.x));
    r.y = ((p0.y + p1.y) + (p2.y + p3.y)) + ((p4.y + p5.y) + (p6.y + p7.y));
    ((float2*)out)[e] = r;
}

// ---------------------------------------------------------------------------

extern "C" void kernel_launch(void* const* d_in, const int* in_sizes, int n_in,
                              void* d_out, int out_size) {
    const float* x  = (const float*)d_in[0];
    const float* W  = (const float*)d_in[1];
    const float* B  = (const float*)d_in[2];
    const float* Wr = (const float*)d_in[3];
    const float* Wi = (const float*)d_in[4];
    float* out = (float*)d_out;

    cudaFuncSetAttribute(k_main, cudaFuncAttributeMaxDynamicSharedMemorySize, SMEM_MAIN);

    k_init<<<18 + 1024 + 256, 256>>>(W, B);
    k_main<<<296, 256, SMEM_MAIN>>>(x);
    k_gemm4<<<dim3(4, 8, 16), 256>>>(Wr, Wi);
    k_reduce<<<512, 256>>>(out);
}